// round 1
// baseline (speedup 1.0000x reference)
#include <cuda_runtime.h>
#include <math.h>

#define Bn   8
#define Cn   16
#define Fn   256
#define F2n  129
#define Tn   512
#define BTn  4096            // Bn*Tn
#define CINn 32
#define Hn   16
#define NGRP 4128            // 2C * F2
#define PI2  6.283185307179586f

// ---------------- scratch (device globals; no runtime allocation) ----------------
__device__ __align__(128) float  g_xt  [(size_t)Bn*Tn*Cn*Fn];      // x transposed: (b,t,c,f)
__device__ __align__(128) float  g_y   [(size_t)BTn*F2n*CINn];     // z -> normalized y: (bt,k,ch)
__device__ __align__(128) float2 g_xf  [(size_t)BTn*Cn*F2n];       // X(f): (bt,c,k) complex
__device__ __align__(128) float  g_hcat[(size_t)BTn*F2n*2*Hn];     // LSTM out concat: (bt,k,32)
__device__ __align__(128) float  g_outt[(size_t)Bn*Tn*Cn*Fn];      // output transposed (b,t,c,f)
__device__ __align__(128) float2 g_part[(size_t)BTn*16];           // per-warp (sum,sumsq)
__device__ __align__(128) float2 g_stats[BTn];                     // (mean, rstd)

// ---------------- helpers ----------------
__device__ __forceinline__ float fsigmoid(float x) {
    return __fdividef(1.0f, 1.0f + __expf(-x));
}
__device__ __forceinline__ float ftanh_(float x) {
    float e = __expf(2.0f * x);                 // inf-safe: e=inf -> 1, e=0 -> -1
    return 1.0f - __fdividef(2.0f, e + 1.0f);
}

// ---------------- K0: transpose x (B,C,F,T) -> (B,T,C,F) ----------------
__global__ void ktrans_in(const float* __restrict__ x) {
    __shared__ float tile[32][33];
    int bc = blockIdx.z;                 // b*C + c
    int f0 = blockIdx.x * 32, t0 = blockIdx.y * 32;
    int tx = threadIdx.x, ty = threadIdx.y;
    const float* src = x + (size_t)bc * Fn * Tn;
#pragma unroll
    for (int i = 0; i < 32; i += 8)
        tile[ty + i][tx] = src[(size_t)(f0 + ty + i) * Tn + t0 + tx];
    __syncthreads();
    int b = bc >> 4, c = bc & 15;
    float* dst = g_xt + (size_t)b * Tn * Cn * Fn + (size_t)c * Fn;
#pragma unroll
    for (int i = 0; i < 32; i += 8)
        dst[(size_t)(t0 + ty + i) * (Cn * Fn) + f0 + tx] = tile[tx][ty + i];
}

// ---------------- K1: forward rfft 256 -> 129, per warp one (bt,c) ----------------
// two-stage radix-16:  X[k] = sum_{n0} e^{-2pi i n0 k/256} * sum_{n1} x[16 n1+n0] e^{-2pi i n1 (k%16)/16}
__global__ __launch_bounds__(256) void kfft_fwd() {
    __shared__ float tc[256], ts[256];        // e^{i 2pi j/256}: cos, sin
    __shared__ float t16c[256], t16s[256];    // [n1*16+m] : cos/sin(2pi n1 m/16)
    __shared__ float  xs[8][256];
    __shared__ float2 As[8][256];
    int tid = threadIdx.x;
    {
        float s, c;
        sincosf((float)tid * (PI2 / 256.0f), &s, &c);
        tc[tid] = c; ts[tid] = s;
        int n1 = tid >> 4, m = tid & 15;
        sincosf((float)((n1 * m) & 15) * (PI2 / 16.0f), &s, &c);
        t16c[tid] = c; t16s[tid] = s;
    }
    __syncthreads();

    int wi = tid >> 5, l = tid & 31;
    int g  = blockIdx.x * 8 + wi;             // transform id = bt*16 + c
    int bt = g >> 4, c = g & 15;

    const float* __restrict__ xrow = g_xt + (size_t)g * 256;
#pragma unroll
    for (int q = 0; q < 8; q++) xs[wi][l + 32 * q] = xrow[l + 32 * q];
    __syncwarp();

    // stage 1: real-input 16-pt DFTs.  m = (l&15) is constant per lane -> preload twiddle row
    int m16 = l & 15;
    float c16[16], s16[16];
#pragma unroll
    for (int n1 = 0; n1 < 16; n1++) { c16[n1] = t16c[n1 * 16 + m16]; s16[n1] = t16s[n1 * 16 + m16]; }
#pragma unroll
    for (int q = 0; q < 8; q++) {
        int p = l + 32 * q, n0 = p >> 4;
        float ar = 0.f, ai = 0.f;
#pragma unroll
        for (int n1 = 0; n1 < 16; n1++) {
            float v = xs[wi][n1 * 16 + n0];
            ar += v * c16[n1];
            ai -= v * s16[n1];
        }
        As[wi][p] = make_float2(ar, ai);
    }
    __syncwarp();

    // stage 2: k = l + 32q (k<=128).  k%16 == l&15 -> preload A row into regs
    float2 Av[16];
#pragma unroll
    for (int n0 = 0; n0 < 16; n0++) Av[n0] = As[wi][n0 * 16 + m16];

    float lsum = 0.f, lsq = 0.f;
#pragma unroll
    for (int q = 0; q < 5; q++) {
        int k = l + 32 * q;
        if (k < 129) {
            float xr = 0.f, xi = 0.f;
#pragma unroll
            for (int n0 = 0; n0 < 16; n0++) {
                int idx = (n0 * k) & 255;
                float cr = tc[idx], si = ts[idx];
                xr += cr * Av[n0].x + si * Av[n0].y;   // Re(e^{-i}A)
                xi += cr * Av[n0].y - si * Av[n0].x;   // Im(e^{-i}A)
            }
            g_y[((size_t)bt * 129 + k) * 32 + c]      = xr;
            g_y[((size_t)bt * 129 + k) * 32 + c + 16] = xi;
            g_xf[((size_t)bt * 16 + c) * 129 + k]     = make_float2(xr, xi);
            lsum += xr + xi;
            lsq  += xr * xr + xi * xi;
        }
    }
#pragma unroll
    for (int o = 16; o > 0; o >>= 1) {
        lsum += __shfl_down_sync(0xffffffffu, lsum, o);
        lsq  += __shfl_down_sync(0xffffffffu, lsq, o);
    }
    if (l == 0) g_part[(size_t)bt * 16 + c] = make_float2(lsum, lsq);
}

// ---------------- K2: deterministic stats reduce -> (mean, rstd) ----------------
__global__ void kstats() {
    int i = blockIdx.x * blockDim.x + threadIdx.x;
    if (i >= BTn) return;
    float s1 = 0.f, s2 = 0.f;
#pragma unroll
    for (int j = 0; j < 16; j++) {
        float2 p = g_part[(size_t)i * 16 + j];
        s1 += p.x; s2 += p.y;
    }
    float mean = s1 * (1.0f / NGRP);
    float var  = (s2 - s1 * s1 * (1.0f / NGRP)) * (1.0f / (NGRP - 1));
    float sd   = sqrtf(fmaxf(var, 0.f)) + 1e-8f;
    g_stats[i] = make_float2(mean, __fdividef(1.0f, sd));
}

// ---------------- K3: normalize in place ----------------
__global__ void knorm(const float* __restrict__ nw, const float* __restrict__ nb) {
    int idx = blockIdx.x * blockDim.x + threadIdx.x;
    if (idx >= BTn * F2n * CINn) return;
    int bt = idx / (F2n * CINn);
    int r  = idx - bt * (F2n * CINn);
    int k  = r >> 5, ch = r & 31;
    float2 st = g_stats[bt];
    float v = g_y[idx];
    g_y[idx] = (v - st.x) * st.y * nw[ch * 129 + k] + nb[ch * 129 + k];
}

// ---------------- K4: bidirectional LSTM; one warp = (seq, dir) ----------------
__global__ void __launch_bounds__(128) klstm(
    const float* __restrict__ wihf, const float* __restrict__ whhf,
    const float* __restrict__ bihf, const float* __restrict__ bhhf,
    const float* __restrict__ wihb, const float* __restrict__ whhb,
    const float* __restrict__ bihb, const float* __restrict__ bhhb) {
    int tid = threadIdx.x, wi = tid >> 5, l = tid & 31;
    int g = blockIdx.x * 4 + wi;
    int s = g >> 1, dir = g & 1;
    const float* wih = dir ? wihb : wihf;
    const float* whh = dir ? whhb : whhf;
    const float* bih = dir ? bihb : bihf;
    const float* bhh = dir ? bhhb : bhhf;

    // lane l owns gate rows l and l+32  (rows: i[0:16) f[16:32) g[32:48) o[48:64))
    float wi0[32], wi1[32], wh0[16], wh1[16];
#pragma unroll
    for (int q = 0; q < 32; q++) { wi0[q] = wih[l * 32 + q]; wi1[q] = wih[(l + 32) * 32 + q]; }
#pragma unroll
    for (int q = 0; q < 16; q++) { wh0[q] = whh[l * 16 + q]; wh1[q] = whh[(l + 32) * 16 + q]; }
    float b0 = bih[l] + bhh[l];
    float b1 = bih[l + 32] + bhh[l + 32];

    float hv[16];
#pragma unroll
    for (int q = 0; q < 16; q++) hv[q] = 0.f;
    float cst = 0.f;

    const float4* __restrict__ ybase =
        reinterpret_cast<const float4*>(g_y + (size_t)s * 129 * 32);

    for (int step = 0; step < 129; step++) {
        int f = dir ? (128 - step) : step;
        const float4* xp = ybase + f * 8;
        float a0m = b0, a1m = b1, a0b = 0.f, a1b = 0.f;
#pragma unroll
        for (int j = 0; j < 8; j++) {
            float4 xv = xp[j];
            a0m += wi0[4 * j    ] * xv.x;  a0b += wi0[4 * j + 1] * xv.y;
            a0m += wi0[4 * j + 2] * xv.z;  a0b += wi0[4 * j + 3] * xv.w;
            a1m += wi1[4 * j    ] * xv.x;  a1b += wi1[4 * j + 1] * xv.y;
            a1m += wi1[4 * j + 2] * xv.z;  a1b += wi1[4 * j + 3] * xv.w;
        }
#pragma unroll
        for (int q = 0; q < 16; q += 2) {
            a0m += wh0[q] * hv[q];  a0b += wh0[q + 1] * hv[q + 1];
            a1m += wh1[q] * hv[q];  a1b += wh1[q + 1] * hv[q + 1];
        }
        float acc0 = a0m + a0b, acc1 = a1m + a1b;
        float a0 = fsigmoid(acc0);                       // i (lanes<16) / f (lanes>=16)
        float a1 = (l < 16) ? ftanh_(acc1) : fsigmoid(acc1);  // g / o
        float fg = __shfl_sync(0xffffffffu, a0, (l + 16) & 31);
        float og = __shfl_sync(0xffffffffu, a1, (l + 16) & 31);
        float cn = fg * cst + a0 * a1;                   // valid for lanes<16
        float hn = og * ftanh_(cn);
        cst = cn;
        if (l < 16)
            g_hcat[((size_t)s * 129 + f) * 32 + (dir << 4) + l] = hn;
#pragma unroll
        for (int q = 0; q < 16; q++) hv[q] = __shfl_sync(0xffffffffu, hn, q);
    }
}

// ---------------- K5: linear + spectrum multiply + irfft; one warp = (bt,c) ----------------
__global__ __launch_bounds__(256) void kinv(const float* __restrict__ lin_w,
                                            const float* __restrict__ lin_b) {
    __shared__ float tc[256], ts[256];
    __shared__ float t16c[256], t16s[256];
    __shared__ float2 Ss[8][256];
    __shared__ float2 Bs[8][256];
    int tid = threadIdx.x;
    {
        float s, c;
        sincosf((float)tid * (PI2 / 256.0f), &s, &c);
        tc[tid] = c; ts[tid] = s;
        int n1 = tid >> 4, m = tid & 15;
        sincosf((float)((n1 * m) & 15) * (PI2 / 16.0f), &s, &c);
        t16c[tid] = c; t16s[tid] = s;
    }
    __syncthreads();

    int wi = tid >> 5, l = tid & 31;
    int g  = blockIdx.x * 8 + wi;
    int bt = g >> 4, c = g & 15;

    float wc0[32], wc1[32];
#pragma unroll
    for (int q = 0; q < 32; q++) { wc0[q] = lin_w[c * 32 + q]; wc1[q] = lin_w[(c + 16) * 32 + q]; }
    float lb0 = lin_b[c], lb1 = lin_b[c + 16];

    // linear + complex multiply, fill hermitian spectrum
#pragma unroll
    for (int q = 0; q < 5; q++) {
        int k = l + 32 * q;
        if (k < 129) {
            const float4* hp = reinterpret_cast<const float4*>(g_hcat + ((size_t)bt * 129 + k) * 32);
            float re = lb0, im = lb1, reb = 0.f, imb = 0.f;
#pragma unroll
            for (int j = 0; j < 8; j++) {
                float4 h4 = hp[j];
                re  += wc0[4 * j    ] * h4.x;  reb += wc0[4 * j + 1] * h4.y;
                re  += wc0[4 * j + 2] * h4.z;  reb += wc0[4 * j + 3] * h4.w;
                im  += wc1[4 * j    ] * h4.x;  imb += wc1[4 * j + 1] * h4.y;
                im  += wc1[4 * j + 2] * h4.z;  imb += wc1[4 * j + 3] * h4.w;
            }
            re += reb; im += imb;
            float2 xf = g_xf[((size_t)bt * 16 + c) * 129 + k];
            float pr = re * xf.x - im * xf.y;
            float pi = re * xf.y + im * xf.x;
            Ss[wi][k] = make_float2(pr, pi);
            if (k >= 1 && k <= 127) Ss[wi][256 - k] = make_float2(pr, -pi);
        }
    }
    __syncwarp();

    // inverse stage 1: B[k0][m] = sum_{k1} S[16k1+k0] e^{+2pi i k1 m/16}
    int m16 = l & 15;
    float c16[16], s16[16];
#pragma unroll
    for (int k1 = 0; k1 < 16; k1++) { c16[k1] = t16c[k1 * 16 + m16]; s16[k1] = t16s[k1 * 16 + m16]; }
#pragma unroll
    for (int q = 0; q < 8; q++) {
        int p = l + 32 * q, k0 = p >> 4;
        float br = 0.f, bi = 0.f;
#pragma unroll
        for (int k1 = 0; k1 < 16; k1++) {
            float2 v = Ss[wi][k1 * 16 + k0];
            br += v.x * c16[k1] - v.y * s16[k1];
            bi += v.x * s16[k1] + v.y * c16[k1];
        }
        Bs[wi][p] = make_float2(br, bi);
    }
    __syncwarp();

    // inverse stage 2 (real output): y[n] = (1/256) sum_{k0} Re(e^{+2pi i n k0/256} B[k0][n%16])
    float2 Bv[16];
#pragma unroll
    for (int k0 = 0; k0 < 16; k0++) Bv[k0] = Bs[wi][k0 * 16 + m16];
    float* orow = g_outt + (size_t)g * 256;
#pragma unroll
    for (int q = 0; q < 8; q++) {
        int n = l + 32 * q;
        float acc = 0.f, accb = 0.f;
#pragma unroll
        for (int k0 = 0; k0 < 16; k0 += 2) {
            int i0 = (k0 * n) & 255, i1 = ((k0 + 1) * n) & 255;
            acc  += Bv[k0    ].x * tc[i0] - Bv[k0    ].y * ts[i0];
            accb += Bv[k0 + 1].x * tc[i1] - Bv[k0 + 1].y * ts[i1];
        }
        orow[n] = (acc + accb) * (1.0f / 256.0f);
    }
}

// ---------------- K6: transpose (B,T,C,F) -> (B,C,F,T) ----------------
__global__ void ktrans_out(float* __restrict__ out) {
    __shared__ float tile[32][33];
    int bc = blockIdx.z;
    int b = bc >> 4, c = bc & 15;
    int f0 = blockIdx.x * 32, t0 = blockIdx.y * 32;
    int tx = threadIdx.x, ty = threadIdx.y;
    const float* src = g_outt + (size_t)b * Tn * Cn * Fn + (size_t)c * Fn;
#pragma unroll
    for (int i = 0; i < 32; i += 8)
        tile[ty + i][tx] = src[(size_t)(t0 + ty + i) * (Cn * Fn) + f0 + tx];
    __syncthreads();
    float* dst = out + (size_t)bc * Fn * Tn;
#pragma unroll
    for (int i = 0; i < 32; i += 8)
        dst[(size_t)(f0 + ty + i) * Tn + t0 + tx] = tile[tx][ty + i];
}

// ---------------- launch ----------------
extern "C" void kernel_launch(void* const* d_in, const int* in_sizes, int n_in,
                              void* d_out, int out_size) {
    const float* x      = (const float*)d_in[0];
    const float* norm_w = (const float*)d_in[1];
    const float* norm_b = (const float*)d_in[2];
    const float* w_ih_f = (const float*)d_in[3];
    const float* w_hh_f = (const float*)d_in[4];
    const float* b_ih_f = (const float*)d_in[5];
    const float* b_hh_f = (const float*)d_in[6];
    const float* w_ih_b = (const float*)d_in[7];
    const float* w_hh_b = (const float*)d_in[8];
    const float* b_ih_b = (const float*)d_in[9];
    const float* b_hh_b = (const float*)d_in[10];
    const float* lin_w  = (const float*)d_in[11];
    const float* lin_b  = (const float*)d_in[12];
    float* out = (float*)d_out;

    dim3 tgrid(Fn / 32, Tn / 32, Bn * Cn);
    dim3 tblk(32, 8);

    ktrans_in<<<tgrid, tblk>>>(x);
    kfft_fwd<<<(BTn * 16) / 8, 256>>>();
    kstats<<<(BTn + 255) / 256, 256>>>();
    knorm<<<(BTn * F2n * CINn + 255) / 256, 256>>>(norm_w, norm_b);
    klstm<<<(BTn * 2) / 4, 128>>>(w_ih_f, w_hh_f, b_ih_f, b_hh_f,
                                  w_ih_b, w_hh_b, b_ih_b, b_hh_b);
    kinv<<<(BTn * 16) / 8, 256>>>(lin_w, lin_b);
    ktrans_out<<<tgrid, tblk>>>(out);
}